// round 3
// baseline (speedup 1.0000x reference)
#include <cuda_runtime.h>
#include <cstdint>
#include <cstddef>

#define Bb 512
#define Tt 512
#define Ff 128
#define Uu 256
#define G4 1024   // 4*U

typedef unsigned long long ull;

// ---------------- f32x2 helpers (Blackwell packed fp32) ----------------
__device__ __forceinline__ ull ffma2(ull a, ull b, ull c) {
    ull d;
    asm("fma.rn.f32x2 %0, %1, %2, %3;" : "=l"(d) : "l"(a), "l"(b), "l"(c));
    return d;
}
__device__ __forceinline__ ull pack2(float x, float y) {
    ull d; asm("mov.b64 %0, {%1, %2};" : "=l"(d) : "f"(x), "f"(y)); return d;
}
__device__ __forceinline__ float2 unpack2(ull v) {
    float2 r; asm("mov.b64 {%0, %1}, %2;" : "=f"(r.x), "=f"(r.y) : "l"(v)); return r;
}

// ---------------- device scratch ----------------
__device__ float g_xz[(size_t)Bb * Tt * G4];   // [b][t][col] precomputed x@kernel+bias
__device__ float g_h[2][Bb][Uu];               // double-buffered hidden state
__device__ unsigned g_bar;

__global__ void reset_kernel() {
    size_t i = (size_t)blockIdx.x * blockDim.x + threadIdx.x;
    if (i < (size_t)Bb * Uu) (&g_h[0][0][0])[i] = 0.0f;
    if (i == 0) g_bar = 0u;
}

// ---------------- Phase 1: XZ = x @ kernel + bias (f32x2) ----------------
#define P1_BM 128
#define P1_BN 64
#define P1_BK 32

__global__ __launch_bounds__(256) void xz_gemm(const float* __restrict__ x,
                                               const float* __restrict__ wk,
                                               const float* __restrict__ bias) {
    __shared__ float2 As2[P1_BK][130];   // duplicated (a,a); pad row to 130
    __shared__ float  Bs[P1_BK][68];
    int tid  = threadIdx.x;
    int nblk = blockIdx.x, mblk = blockIdx.y;
    const float* xblk = x + (size_t)mblk * P1_BM * Ff;
    int tn = tid & 15, tm = tid >> 4;    // n0 = 4*tn, m0 = 8*tm

    ull acc[8][2];
    {
        ull b0 = pack2(bias[nblk * P1_BN + 4 * tn + 0], bias[nblk * P1_BN + 4 * tn + 1]);
        ull b1 = pack2(bias[nblk * P1_BN + 4 * tn + 2], bias[nblk * P1_BN + 4 * tn + 3]);
#pragma unroll
        for (int i = 0; i < 8; i++) { acc[i][0] = b0; acc[i][1] = b1; }
    }

    int lm = tid >> 3, lq = tid & 7;
    for (int kk = 0; kk < Ff; kk += P1_BK) {
#pragma unroll
        for (int p = 0; p < 4; p++) {
            float4 v = *(const float4*)(xblk + (size_t)(lm + 32 * p) * Ff + kk + 4 * lq);
            As2[4 * lq + 0][lm + 32 * p] = make_float2(v.x, v.x);
            As2[4 * lq + 1][lm + 32 * p] = make_float2(v.y, v.y);
            As2[4 * lq + 2][lm + 32 * p] = make_float2(v.z, v.z);
            As2[4 * lq + 3][lm + 32 * p] = make_float2(v.w, v.w);
        }
#pragma unroll
        for (int i = 0; i < 2; i++) {
            int fi = tid * 2 + i;
            int r = fi >> 4, c = fi & 15;
            float4 v = *(const float4*)(wk + (size_t)(kk + r) * G4 + nblk * P1_BN + 4 * c);
            *(float4*)&Bs[r][4 * c] = v;
        }
        __syncthreads();
#pragma unroll
        for (int k = 0; k < P1_BK; k++) {
            ulonglong2 bv = *(const ulonglong2*)&Bs[k][4 * tn];   // (n0,n1),(n2,n3)
#pragma unroll
            for (int p = 0; p < 4; p++) {
                ulonglong2 av = *(const ulonglong2*)&As2[k][8 * tm + 2 * p];  // dup a(2p), dup a(2p+1)
                acc[2 * p + 0][0] = ffma2(av.x, bv.x, acc[2 * p + 0][0]);
                acc[2 * p + 0][1] = ffma2(av.x, bv.y, acc[2 * p + 0][1]);
                acc[2 * p + 1][0] = ffma2(av.y, bv.x, acc[2 * p + 1][0]);
                acc[2 * p + 1][1] = ffma2(av.y, bv.y, acc[2 * p + 1][1]);
            }
        }
        __syncthreads();
    }
    float* od = g_xz + ((size_t)mblk * P1_BM) * G4 + nblk * P1_BN;
#pragma unroll
    for (int i = 0; i < 8; i++) {
        float2 a = unpack2(acc[i][0]);
        float2 b = unpack2(acc[i][1]);
        *(float4*)(od + (size_t)(8 * tm + i) * G4 + 4 * tn) = make_float4(a.x, a.y, b.x, b.y);
    }
}

// ---------------- Phase 2: persistent recurrence (f32x2) ----------------
// 128 CTAs = 16 batch-groups x 8 unit-groups. CTA: 32 batches x 32 units.
// Thread map: lane = batch, warp w -> units 4w..4w+3 (x4 gates).
// SMEM: Wr [256][128] interleaved [k][u*4+g] (128KB)
//       Hs2 [32][258] float2, h duplicated (h,h)  (66KB)
//       Xs  2 x [32][132] xz tile double buffer (33KB, cp.async prefetch)
#define RC_CTAS 128
#define HS_STRIDE 258   // float2 units
#define XS_STRIDE 132
#define XS_BUF (32 * XS_STRIDE)

__device__ __forceinline__ void cp_async16(void* sdst, const void* gsrc) {
    unsigned sa = (unsigned)__cvta_generic_to_shared(sdst);
    asm volatile("cp.async.cg.shared.global [%0], [%1], 16;" :: "r"(sa), "l"(gsrc));
}

__global__ __launch_bounds__(256, 1) void lstm_rec(const float* __restrict__ rk,
                                                   const float* __restrict__ dw,
                                                   const float* __restrict__ db,
                                                   float* __restrict__ out) {
    extern __shared__ float sm[];
    float*  Wr  = sm;                         // 32768 floats
    float2* Hs2 = (float2*)(sm + 32768);      // 32*258 float2 = 16512 floats
    float*  Xs  = sm + 32768 + 16512;         // 2*4224 floats

    int tid   = threadIdx.x;
    int bg    = blockIdx.x >> 3;
    int cg    = blockIdx.x & 7;
    int bbase = bg * 32;
    int ubase = cg * 32;

    // one-time: load + interleave weight slice Wr[k][u*4+g] = rk[k][g*256+ubase+u]
    for (int idx = tid; idx < 256 * 128; idx += 256) {
        int k = idx >> 7, n = idx & 127;
        int u = n >> 2, g = n & 3;
        Wr[idx] = rk[(size_t)k * G4 + g * Uu + ubase + u];
    }

    int w = tid >> 5, l = tid & 31;           // warp -> unit group, lane -> batch
    float c[4] = {0.f, 0.f, 0.f, 0.f};

    int sb = tid >> 3, sq = tid & 7;          // staging maps

    // prefetch xz tile for t=0 into buf 0
    {
#pragma unroll
        for (int i = 0; i < 4; i++) {
            int flat4 = tid + 256 * i;
            int bb = flat4 >> 5, rest = flat4 & 31, g = rest >> 3, u4 = rest & 7;
            const float* gsrc = g_xz + ((size_t)(bbase + bb) * Tt + 0) * G4 + g * Uu + ubase + 4 * u4;
            cp_async16(Xs + bb * XS_STRIDE + g * 32 + 4 * u4, gsrc);
        }
        asm volatile("cp.async.commit_group;" ::: "memory");
    }

    unsigned target = 0;

    for (int t = 0; t < Tt; t++) {
        int cur = t & 1, nxt = cur ^ 1;

        // stage h_prev (duplicated) into Hs2
        {
            const float* hsrc = &g_h[cur][bbase + sb][0];
            float2* hdst = Hs2 + sb * HS_STRIDE;
#pragma unroll
            for (int j = 0; j < 8; j++) {
                float4 v = *(const float4*)(hsrc + 4 * sq + 32 * j);
                *(float4*)(hdst + 4 * sq + 32 * j)     = make_float4(v.x, v.x, v.y, v.y);
                *(float4*)(hdst + 4 * sq + 32 * j + 2) = make_float4(v.z, v.z, v.w, v.w);
            }
        }
        // prefetch next xz tile
        if (t + 1 < Tt) {
#pragma unroll
            for (int i = 0; i < 4; i++) {
                int flat4 = tid + 256 * i;
                int bb = flat4 >> 5, rest = flat4 & 31, g = rest >> 3, u4 = rest & 7;
                const float* gsrc = g_xz + ((size_t)(bbase + bb) * Tt + (t + 1)) * G4 + g * Uu + ubase + 4 * u4;
                cp_async16(Xs + nxt * XS_BUF + bb * XS_STRIDE + g * 32 + 4 * u4, gsrc);
            }
            asm volatile("cp.async.commit_group;" ::: "memory");
            asm volatile("cp.async.wait_group 1;" ::: "memory");   // wait for buf[cur]
        } else {
            asm volatile("cp.async.wait_group 0;" ::: "memory");
        }
        __syncthreads();   // Hs2 + Xs[cur] ready

        // acc init from xz tile
        ull acc[4][2];
        {
            const float* xc = Xs + cur * XS_BUF + l * XS_STRIDE;
#pragma unroll
            for (int i = 0; i < 4; i++) {
                int u = 4 * w + i;
                acc[i][0] = pack2(xc[0 * 32 + u], xc[1 * 32 + u]);
                acc[i][1] = pack2(xc[2 * 32 + u], xc[3 * 32 + u]);
            }
        }

        // GEMM: acc[u][pair] += h[k] * Wr[k][u][pair]
        const float2* hp = Hs2 + l * HS_STRIDE;
        const float*  wp = Wr + 16 * w;
#pragma unroll 4
        for (int k2 = 0; k2 < 128; k2++) {
            ulonglong2 hh = *(const ulonglong2*)(hp + 2 * k2);   // dup h(2k2), dup h(2k2+1)
            const float* w0 = wp + 2 * k2 * 128;
#pragma unroll
            for (int i = 0; i < 4; i++) {
                ulonglong2 wv0 = *(const ulonglong2*)(w0 + 4 * i);
                ulonglong2 wv1 = *(const ulonglong2*)(w0 + 128 + 4 * i);
                acc[i][0] = ffma2(hh.x, wv0.x, acc[i][0]);
                acc[i][1] = ffma2(hh.x, wv0.y, acc[i][1]);
                acc[i][0] = ffma2(hh.y, wv1.x, acc[i][0]);
                acc[i][1] = ffma2(hh.y, wv1.y, acc[i][1]);
            }
        }

        // gates
        float hn[4];
#pragma unroll
        for (int i = 0; i < 4; i++) {
            float2 p01 = unpack2(acc[i][0]);   // (i, f)
            float2 p23 = unpack2(acc[i][1]);   // (g, o)
            float ig = 1.f / (1.f + __expf(-p01.x));
            float fg = 1.f / (1.f + __expf(-p01.y));
            float gg = fmaxf(p23.x, 0.f);
            float og = 1.f / (1.f + __expf(-p23.y));
            float cn = fg * c[i] + ig * gg;
            c[i] = cn;
            hn[i] = og * fmaxf(cn, 0.f);
        }

        // guard: everyone done reading Xs[cur] + Hs2 before reuse as bounce buf
        __syncthreads();

        // bounce hn through smem for coalesced global write (reuse Xs[cur])
        {
            float* Hw = Xs + cur * XS_BUF;     // [32][36] layout
#pragma unroll
            for (int i = 0; i < 4; i++) Hw[l * 36 + 4 * w + i] = hn[i];
        }
        __syncthreads();
        {
            const float* Hw = Xs + cur * XS_BUF;
            float4 hv = *(const float4*)(Hw + sb * 36 + 4 * sq);
            *(float4*)(&g_h[nxt][bbase + sb][ubase + 4 * sq]) = hv;
        }

        // global barrier (all 128 CTAs co-resident)
        __syncthreads();
        if (tid == 0) {
            __threadfence();
            atomicAdd(&g_bar, 1u);
            target += RC_CTAS;
            while (*((volatile unsigned*)&g_bar) < target) { }
            __threadfence();
        }
        __syncthreads();
    }

    // final dense: out[b] = h_T[b,:] . dw + db  (T even -> h_T in g_h[0])
    if (cg == 0) {
        int b = tid >> 3, r = tid & 7;
        const float* hrow = &g_h[0][bbase + b][0];
        float s = 0.f;
#pragma unroll
        for (int j = 0; j < 32; j++) s += hrow[r + 8 * j] * dw[r + 8 * j];
        s += __shfl_down_sync(0xffffffffu, s, 4);
        s += __shfl_down_sync(0xffffffffu, s, 2);
        s += __shfl_down_sync(0xffffffffu, s, 1);
        if (r == 0) out[bbase + b] = s + db[0];
    }
}

// ---------------- launch ----------------
extern "C" void kernel_launch(void* const* d_in, const int* in_sizes, int n_in,
                              void* d_out, int out_size) {
    const float* x    = (const float*)d_in[0];
    const float* wk   = (const float*)d_in[1];
    const float* rk   = (const float*)d_in[2];
    const float* bias = (const float*)d_in[3];
    const float* dw   = (const float*)d_in[4];
    const float* db   = (const float*)d_in[5];
    float* out = (float*)d_out;

    size_t smem = (size_t)(32768 + 16512 + 2 * XS_BUF) * sizeof(float);  // 230,912 B
    cudaFuncSetAttribute(lstm_rec, cudaFuncAttributeMaxDynamicSharedMemorySize, (int)smem);

    reset_kernel<<<(Bb * Uu + 255) / 256, 256>>>();
    xz_gemm<<<dim3(G4 / P1_BN, (Bb * Tt) / P1_BM), 256>>>(x, wk, bias);
    lstm_rec<<<RC_CTAS, 256, smem>>>(rk, dw, db, out);
}

// round 5
// speedup vs baseline: 2.3681x; 2.3681x over previous
#include <cuda_runtime.h>
#include <cuda_bf16.h>
#include <cstdint>
#include <cstddef>

#define Bb 512
#define Tt 512
#define Ff 128
#define Uu 256
#define G4 1024   // 4*U

// ---------------- device scratch ----------------
__device__ float g_xz[(size_t)Bb * Tt * G4];   // [b][t][col] precomputed x@kernel+bias
__device__ float g_h[2][Bb][Uu];               // double-buffered hidden state
__device__ unsigned g_bar;

__global__ void reset_kernel() {
    size_t i = (size_t)blockIdx.x * blockDim.x + threadIdx.x;
    if (i < (size_t)Bb * Uu) (&g_h[0][0][0])[i] = 0.0f;
    if (i == 0) g_bar = 0u;
}

// ---------------- helpers ----------------
__device__ __forceinline__ void mma_bf16(float& d0, float& d1, float& d2, float& d3,
                                         unsigned a0, unsigned a1, unsigned a2, unsigned a3,
                                         unsigned b0, unsigned b1) {
    asm volatile("mma.sync.aligned.m16n8k16.row.col.f32.bf16.bf16.f32 "
                 "{%0,%1,%2,%3}, {%4,%5,%6,%7}, {%8,%9}, {%0,%1,%2,%3};"
                 : "+f"(d0), "+f"(d1), "+f"(d2), "+f"(d3)
                 : "r"(a0), "r"(a1), "r"(a2), "r"(a3), "r"(b0), "r"(b1));
}
__device__ __forceinline__ unsigned pk2(__nv_bfloat16 x, __nv_bfloat16 y) {
    __nv_bfloat162 t; t.x = x; t.y = y;
    return *reinterpret_cast<unsigned*>(&t);
}
__device__ __forceinline__ void split1(float v, __nv_bfloat16& h, __nv_bfloat16& l) {
    h = __float2bfloat16_rn(v);
    l = __float2bfloat16_rn(v - __bfloat162float(h));
}
__device__ __forceinline__ void cp_async16(void* sdst, const void* gsrc) {
    unsigned sa = (unsigned)__cvta_generic_to_shared(sdst);
    asm volatile("cp.async.cg.shared.global [%0], [%1], 16;" :: "r"(sa), "l"(gsrc));
}

// ================= Phase 1: XZ = x @ kernel + bias (bf16x3 mma) =================
// CTA tile 128M x 128N, K=128 single shot. 512 threads = 16 warps (4x4),
// warp tile 32x32. A,B split to bf16 hi/lo in SMEM, 3 mma passes.
#define P1_STR 136   // bf16 row stride (k-contiguous)

__global__ __launch_bounds__(512) void xz_gemm(const float* __restrict__ x,
                                               const float* __restrict__ wk,
                                               const float* __restrict__ bias) {
    extern __shared__ char smc[];
    __nv_bfloat16* Ahi = (__nv_bfloat16*)smc;                   // [128][136]
    __nv_bfloat16* Alo = (__nv_bfloat16*)(smc + 34816);
    __nv_bfloat16* Bhi = (__nv_bfloat16*)(smc + 69632);         // [128 n][136 k]
    __nv_bfloat16* Blo = (__nv_bfloat16*)(smc + 104448);

    int tid  = threadIdx.x;
    int nblk = blockIdx.x, mblk = blockIdx.y;
    const float* xblk = x + (size_t)mblk * 128 * Ff;
    const float* wcol = wk + (size_t)nblk * 128;

    // A fill: x tile [128][128] fp32 -> split
    {
        int r = tid >> 2, q = tid & 3;
        const float* xr = xblk + (size_t)r * Ff;
#pragma unroll
        for (int jj = 0; jj < 8; jj++) {
            int col = 4 * q + 16 * jj;
            float4 v = *(const float4*)(xr + col);
            __nv_bfloat16 h0, h1, h2, h3, l0, l1, l2, l3;
            split1(v.x, h0, l0); split1(v.y, h1, l1);
            split1(v.z, h2, l2); split1(v.w, h3, l3);
            *(unsigned*)(Ahi + r * P1_STR + col)     = pk2(h0, h1);
            *(unsigned*)(Ahi + r * P1_STR + col + 2) = pk2(h2, h3);
            *(unsigned*)(Alo + r * P1_STR + col)     = pk2(l0, l1);
            *(unsigned*)(Alo + r * P1_STR + col + 2) = pk2(l2, l3);
        }
    }
    // B fill: Bs[n][k] = wk[k][nblk*128+n] -> split
#pragma unroll
    for (int i = 0; i < 32; i++) {
        int flat = tid + 512 * i;
        int k = flat >> 7, n = flat & 127;
        float v = wcol[(size_t)k * G4 + n];
        __nv_bfloat16 h, l; split1(v, h, l);
        Bhi[n * P1_STR + k] = h;
        Blo[n * P1_STR + k] = l;
    }
    __syncthreads();

    int w = tid >> 5, lane = tid & 31;
    int wm = w >> 2, wn = w & 3;
    int g = lane >> 2, tq = lane & 3;
    int mb = 32 * wm, nb = 32 * wn;

    float acc[2][4][4];
#pragma unroll
    for (int ni = 0; ni < 4; ni++) {
        float2 bv = *(const float2*)(bias + nblk * 128 + nb + 8 * ni + 2 * tq);
#pragma unroll
        for (int mi = 0; mi < 2; mi++) {
            acc[mi][ni][0] = bv.x; acc[mi][ni][1] = bv.y;
            acc[mi][ni][2] = bv.x; acc[mi][ni][3] = bv.y;
        }
    }

#pragma unroll 2
    for (int kc = 0; kc < 128; kc += 16) {
        unsigned bh[4][2], bl[4][2];
#pragma unroll
        for (int ni = 0; ni < 4; ni++) {
            const __nv_bfloat16* bp = Bhi + (nb + 8 * ni + g) * P1_STR + kc + 2 * tq;
            bh[ni][0] = *(const unsigned*)bp;
            bh[ni][1] = *(const unsigned*)(bp + 8);
            const __nv_bfloat16* bq = Blo + (nb + 8 * ni + g) * P1_STR + kc + 2 * tq;
            bl[ni][0] = *(const unsigned*)bq;
            bl[ni][1] = *(const unsigned*)(bq + 8);
        }
#pragma unroll
        for (int mi = 0; mi < 2; mi++) {
            const __nv_bfloat16* ap = Ahi + (mb + 16 * mi + g) * P1_STR + kc + 2 * tq;
            unsigned a0 = *(const unsigned*)ap;
            unsigned a1 = *(const unsigned*)(ap + 8 * P1_STR);
            unsigned a2 = *(const unsigned*)(ap + 8);
            unsigned a3 = *(const unsigned*)(ap + 8 * P1_STR + 8);
            const __nv_bfloat16* aq = Alo + (mb + 16 * mi + g) * P1_STR + kc + 2 * tq;
            unsigned e0 = *(const unsigned*)aq;
            unsigned e1 = *(const unsigned*)(aq + 8 * P1_STR);
            unsigned e2 = *(const unsigned*)(aq + 8);
            unsigned e3 = *(const unsigned*)(aq + 8 * P1_STR + 8);
#pragma unroll
            for (int ni = 0; ni < 4; ni++) {
                mma_bf16(acc[mi][ni][0], acc[mi][ni][1], acc[mi][ni][2], acc[mi][ni][3],
                         a0, a1, a2, a3, bh[ni][0], bh[ni][1]);
                mma_bf16(acc[mi][ni][0], acc[mi][ni][1], acc[mi][ni][2], acc[mi][ni][3],
                         a0, a1, a2, a3, bl[ni][0], bl[ni][1]);
                mma_bf16(acc[mi][ni][0], acc[mi][ni][1], acc[mi][ni][2], acc[mi][ni][3],
                         e0, e1, e2, e3, bh[ni][0], bh[ni][1]);
            }
        }
    }

    float* od = g_xz + ((size_t)mblk * 128) * G4 + nblk * 128;
#pragma unroll
    for (int mi = 0; mi < 2; mi++) {
#pragma unroll
        for (int ni = 0; ni < 4; ni++) {
            int row = mb + 16 * mi + g, col = nb + 8 * ni + 2 * tq;
            *(float2*)(od + (size_t)row * G4 + col)       = make_float2(acc[mi][ni][0], acc[mi][ni][1]);
            *(float2*)(od + (size_t)(row + 8) * G4 + col) = make_float2(acc[mi][ni][2], acc[mi][ni][3]);
        }
    }
}

// ================= Phase 2: persistent recurrence (bf16x3 mma) =================
// 128 CTAs = 16 batch-groups x 8 col-groups; CTA = 32 batches x 128 gate-cols
// (local col j = gate*32 + u, u local unit 0..31). 256 threads / 8 warps.
#define RC_CTAS 128
#define WS 264     // W smem stride (bf16)
#define AS 264     // A(h) smem stride (bf16)
#define XSS 132    // xz smem stride (floats)
#define XSBUF (32 * XSS)
#define ZSS 136    // z smem stride (floats)

__global__ __launch_bounds__(256, 1) void lstm_rec(const float* __restrict__ rk,
                                                   const float* __restrict__ dw,
                                                   const float* __restrict__ db,
                                                   float* __restrict__ out) {
    extern __shared__ char smc[];
    __nv_bfloat16* Wh = (__nv_bfloat16*)smc;                    // [128][264]
    __nv_bfloat16* Wl = (__nv_bfloat16*)(smc + 67584);
    __nv_bfloat16* Ah = (__nv_bfloat16*)(smc + 135168);         // [32][264]
    __nv_bfloat16* Al = (__nv_bfloat16*)(smc + 152064);
    float* xs = (float*)(smc + 168960);                         // [2][32][132]
    float* zs = (float*)(smc + 202752);                         // [32][136]

    int tid   = threadIdx.x;
    int bg    = blockIdx.x >> 3;
    int cg    = blockIdx.x & 7;
    int bbase = bg * 32;
    int ubase = cg * 32;

    // one-time: weight slice -> bf16 hi/lo, layout Wh[j][k], j = gate*32 + u
    for (int i = tid; i < 128 * 256; i += 256) {
        int j = i >> 8, k = i & 255;
        int gate = j >> 5, u = j & 31;
        float v = rk[(size_t)k * G4 + gate * Uu + ubase + u];
        __nv_bfloat16 h, l; split1(v, h, l);
        Wh[j * WS + k] = h;
        Wl[j * WS + k] = l;
    }

    int w = tid >> 5, lane = tid & 31;
    int g = lane >> 2, tq = lane & 3;
    int nb = 16 * w;                 // warp covers local cols [16w,16w+16)
    int gb = tid >> 3;               // gate-layer batch
    int gu = (tid & 7) * 4;          // gate-layer unit base
    float cst[4] = {0.f, 0.f, 0.f, 0.f};

    // prefetch xz tile for t=0 into xs buf 0
#pragma unroll
    for (int i = 0; i < 4; i++) {
        int flat4 = tid + 256 * i;
        int bbq = flat4 >> 5, rest = flat4 & 31, gg = rest >> 3, u4 = rest & 7;
        const float* gsrc = g_xz + ((size_t)(bbase + bbq) * Tt + 0) * G4 + gg * Uu + ubase + 4 * u4;
        cp_async16(xs + bbq * XSS + gg * 32 + 4 * u4, gsrc);
    }
    asm volatile("cp.async.commit_group;" ::: "memory");

    unsigned target = 0;

    for (int t = 0; t < Tt; t++) {
        int cur = t & 1, nxt = cur ^ 1;

        // fill A tiles: h (fp32) from g_h[cur] -> bf16 hi/lo
        {
            int r = tid >> 3, q = tid & 7;
            const float* hrow = &g_h[cur][bbase + r][0];
#pragma unroll
            for (int jj = 0; jj < 8; jj++) {
                int col = 4 * q + 32 * jj;
                float4 v = *(const float4*)(hrow + col);
                __nv_bfloat16 h0, h1, h2, h3, l0, l1, l2, l3;
                split1(v.x, h0, l0); split1(v.y, h1, l1);
                split1(v.z, h2, l2); split1(v.w, h3, l3);
                *(unsigned*)(Ah + r * AS + col)     = pk2(h0, h1);
                *(unsigned*)(Ah + r * AS + col + 2) = pk2(h2, h3);
                *(unsigned*)(Al + r * AS + col)     = pk2(l0, l1);
                *(unsigned*)(Al + r * AS + col + 2) = pk2(l2, l3);
            }
        }
        // prefetch next xz tile
        if (t + 1 < Tt) {
#pragma unroll
            for (int i = 0; i < 4; i++) {
                int flat4 = tid + 256 * i;
                int bbq = flat4 >> 5, rest = flat4 & 31, gg = rest >> 3, u4 = rest & 7;
                const float* gsrc = g_xz + ((size_t)(bbase + bbq) * Tt + (t + 1)) * G4 + gg * Uu + ubase + 4 * u4;
                cp_async16(xs + nxt * XSBUF + bbq * XSS + gg * 32 + 4 * u4, gsrc);
            }
            asm volatile("cp.async.commit_group;" ::: "memory");
            asm volatile("cp.async.wait_group 1;" ::: "memory");
        } else {
            asm volatile("cp.async.wait_group 0;" ::: "memory");
        }
        __syncthreads();   // A tiles + xs[cur] (+ W on t=0) ready

        // acc init from xz tile
        float acc[2][2][4];
#pragma unroll
        for (int mi = 0; mi < 2; mi++) {
#pragma unroll
            for (int ni = 0; ni < 2; ni++) {
                const float* zp = xs + cur * XSBUF + (16 * mi + g) * XSS + nb + 8 * ni + 2 * tq;
                float2 a = *(const float2*)zp;
                float2 b = *(const float2*)(zp + 8 * XSS);
                acc[mi][ni][0] = a.x; acc[mi][ni][1] = a.y;
                acc[mi][ni][2] = b.x; acc[mi][ni][3] = b.y;
            }
        }

        // K loop: z += h @ Wr (3-pass bf16 split)
#pragma unroll 4
        for (int kc = 0; kc < 256; kc += 16) {
            unsigned bh[2][2], bl[2][2];
#pragma unroll
            for (int ni = 0; ni < 2; ni++) {
                const __nv_bfloat16* bp = Wh + (nb + 8 * ni + g) * WS + kc + 2 * tq;
                bh[ni][0] = *(const unsigned*)bp;
                bh[ni][1] = *(const unsigned*)(bp + 8);
                const __nv_bfloat16* bq = Wl + (nb + 8 * ni + g) * WS + kc + 2 * tq;
                bl[ni][0] = *(const unsigned*)bq;
                bl[ni][1] = *(const unsigned*)(bq + 8);
            }
#pragma unroll
            for (int mi = 0; mi < 2; mi++) {
                const __nv_bfloat16* ap = Ah + (16 * mi + g) * AS + kc + 2 * tq;
                unsigned a0 = *(const unsigned*)ap;
                unsigned a1 = *(const unsigned*)(ap + 8 * AS);
                unsigned a2 = *(const unsigned*)(ap + 8);
                unsigned a3 = *(const unsigned*)(ap + 8 * AS + 8);
                const __nv_bfloat16* aq = Al + (16 * mi + g) * AS + kc + 2 * tq;
                unsigned e0 = *(const unsigned*)aq;
                unsigned e1 = *(const unsigned*)(aq + 8 * AS);
                unsigned e2 = *(const unsigned*)(aq + 8);
                unsigned e3 = *(const unsigned*)(aq + 8 * AS + 8);
#pragma unroll
                for (int ni = 0; ni < 2; ni++) {
                    mma_bf16(acc[mi][ni][0], acc[mi][ni][1], acc[mi][ni][2], acc[mi][ni][3],
                             a0, a1, a2, a3, bh[ni][0], bh[ni][1]);
                    mma_bf16(acc[mi][ni][0], acc[mi][ni][1], acc[mi][ni][2], acc[mi][ni][3],
                             a0, a1, a2, a3, bl[ni][0], bl[ni][1]);
                    mma_bf16(acc[mi][ni][0], acc[mi][ni][1], acc[mi][ni][2], acc[mi][ni][3],
                             e0, e1, e2, e3, bh[ni][0], bh[ni][1]);
                }
            }
        }

        // bounce z through SMEM (decouple gate layout from mma fragments)
#pragma unroll
        for (int mi = 0; mi < 2; mi++) {
#pragma unroll
            for (int ni = 0; ni < 2; ni++) {
                float* zp = zs + (16 * mi + g) * ZSS + nb + 8 * ni + 2 * tq;
                *(float2*)zp            = make_float2(acc[mi][ni][0], acc[mi][ni][1]);
                *(float2*)(zp + 8 * ZSS) = make_float2(acc[mi][ni][2], acc[mi][ni][3]);
            }
        }
        __syncthreads();

        // gate layer: thread -> (batch gb, units gu..gu+3), c-state in regs
        {
            const float* zr = zs + gb * ZSS + gu;
            float4 zi = *(const float4*)(zr + 0);
            float4 zf = *(const float4*)(zr + 32);
            float4 zg = *(const float4*)(zr + 64);
            float4 zo = *(const float4*)(zr + 96);
            float zia[4] = {zi.x, zi.y, zi.z, zi.w};
            float zfa[4] = {zf.x, zf.y, zf.z, zf.w};
            float zga[4] = {zg.x, zg.y, zg.z, zg.w};
            float zoa[4] = {zo.x, zo.y, zo.z, zo.w};
            float hn[4];
#pragma unroll
            for (int e = 0; e < 4; e++) {
                float ig = 1.f / (1.f + __expf(-zia[e]));
                float fg = 1.f / (1.f + __expf(-zfa[e]));
                float gg = fmaxf(zga[e], 0.f);
                float og = 1.f / (1.f + __expf(-zoa[e]));
                float cn = fg * cst[e] + ig * gg;
                cst[e] = cn;
                hn[e] = og * fmaxf(cn, 0.f);
            }
            *(float4*)(&g_h[nxt][bbase + gb][ubase + gu]) =
                make_float4(hn[0], hn[1], hn[2], hn[3]);
        }

        // global barrier (all 128 CTAs co-resident; R1-proven pattern)
        __syncthreads();
        if (tid == 0) {
            __threadfence();
            atomicAdd(&g_bar, 1u);
            target += RC_CTAS;
            while (*((volatile unsigned*)&g_bar) < target) { }
            __threadfence();
        }
        __syncthreads();
    }

    // final dense: out[b] = h_T[b,:] . dw + db   (T even -> h_T in g_h[0])
    if (cg == 0) {
        int b = tid >> 3, r = tid & 7;
        const float* hrow = &g_h[0][bbase + b][0];
        float s = 0.f;
#pragma unroll
        for (int j = 0; j < 32; j++) s += hrow[r + 8 * j] * dw[r + 8 * j];
        s += __shfl_down_sync(0xffffffffu, s, 4);
        s += __shfl_down_sync(0xffffffffu, s, 2);
        s += __shfl_down_sync(0xffffffffu, s, 1);
        if (r == 0) out[bbase + b] = s + db[0];
    }
}

// ---------------- launch ----------------
extern "C" void kernel_launch(void* const* d_in, const int* in_sizes, int n_in,
                              void* d_out, int out_size) {
    const float* x    = (const float*)d_in[0];
    const float* wk   = (const float*)d_in[1];
    const float* rk   = (const float*)d_in[2];
    const float* bias = (const float*)d_in[3];
    const float* dw   = (const float*)d_in[4];
    const float* db   = (const float*)d_in[5];
    float* out = (float*)d_out;

    const int smem1 = 139264;   // phase-1: 4 x [128][136] bf16
    const int smem2 = 220160;   // phase-2: W hi/lo + A hi/lo + xs + zs
    cudaFuncSetAttribute(xz_gemm,  cudaFuncAttributeMaxDynamicSharedMemorySize, smem1);
    cudaFuncSetAttribute(lstm_rec, cudaFuncAttributeMaxDynamicSharedMemorySize, smem2);

    reset_kernel<<<(Bb * Uu + 255) / 256, 256>>>();
    xz_gemm<<<dim3(G4 / 128, (Bb * Tt) / 128), 512, smem1>>>(x, wk, bias);
    lstm_rec<<<RC_CTAS, 256, smem2>>>(rk, dw, db, out);
}